// round 12
// baseline (speedup 1.0000x reference)
#include <cuda_runtime.h>
#include <cfloat>
#include <math.h>

#define BB   4
#define LL   2048
#define NODES (BB*LL)            // 8192
#define TOPK 30
#define NEDGE (NODES*TOPK)       // 245760
#define NTILE (NEDGE/64)         // 3840

// ---------------- scratch ----------------------------------------------------
__device__ float4 g_CaP[NODES];
__device__ float4 g_E1[NODES];
__device__ float4 g_E2[NODES];
__device__ float4 g_E3[NODES];
__device__ float  g_Feat[NTILE*24*64];     // transposed: [tile][feature][edge-in-tile]
__device__ float  g_Ppe[65*128];           // (W_pe+b_pe) @ W_edge[0:16]
__device__ float  g_Pch[2*128];            // (W_ch+b_ch) @ W_edge[39:55]
__device__ float  g_W2r[23*128];           // W_edge rows [16:39)

__device__ __forceinline__ float signf_(float x){ return (x>0.f)?1.f:((x<0.f)?-1.f:0.f); }

#define FMA2(d,a,b,c) asm("fma.rn.f32x2 %0,%1,%2,%3;" : "=l"(d) : "l"(a), "l"(b), "l"(c))
#define ADD2(d,a,b)   asm("add.rn.f32x2 %0,%1,%2;"    : "=l"(d) : "l"(a), "l"(b))
#define MUL2(d,a,b)   asm("mul.rn.f32x2 %0,%1,%2;"    : "=l"(d) : "l"(a), "l"(b))
#define PACK2(d,lo,hi) asm("mov.b64 %0,{%1,%2};" : "=l"(d) : "f"(lo), "f"(hi))
#define UNPK2(lo,hi,s) asm("mov.b64 {%0,%1},%2;" : "=f"(lo), "=f"(hi) : "l"(s))

// ---------------- kernel 1a: pack Ca + per-node frames ----------------------
__global__ void k_prepA(const float* __restrict__ X){
    int n = blockIdx.x*256 + threadIdx.x;
    const float* p = X + (size_t)n*12;
    float Nx=p[0], Ny=p[1], Nz=p[2];
    float Cx=p[3], Cy=p[4], Cz=p[5];
    float Dx=p[6], Dy=p[7], Dz=p[8];
    g_CaP[n] = make_float4(Cx,Cy,Cz,0.f);
    float v1x=Nx-Cx, v1y=Ny-Cy, v1z=Nz-Cz;
    float v2x=Dx-Cx, v2y=Dy-Cy, v2z=Dz-Cz;
    float n1 = sqrtf(v1x*v1x+v1y*v1y+v1z*v1z);
    float i1 = 1.f/(n1+1e-6f);
    float e1x=v1x*i1, e1y=v1y*i1, e1z=v1z*i1;
    float dv = e1x*v2x+e1y*v2y+e1z*v2z;
    float u2x=v2x-dv*e1x, u2y=v2y-dv*e1y, u2z=v2z-dv*e1z;
    float n2 = sqrtf(u2x*u2x+u2y*u2y+u2z*u2z);
    float i2 = 1.f/(n2+1e-6f);
    float e2x=u2x*i2, e2y=u2y*i2, e2z=u2z*i2;
    g_E1[n] = make_float4(e1x,e1y,e1z,0.f);
    g_E2[n] = make_float4(e2x,e2y,e2z,0.f);
    g_E3[n] = make_float4(e1y*e2z-e1z*e2y, e1z*e2x-e1x*e2z, e1x*e2y-e1y*e2x, 0.f);
}

// ---------------- kernel 1b: projection tables ------------------------------
__global__ void k_prepB(const float* __restrict__ W_pe, const float* __restrict__ b_pe,
                        const float* __restrict__ W_ch, const float* __restrict__ b_ch,
                        const float* __restrict__ W_edge){
    int idx = blockIdx.x*256 + threadIdx.x;
    if (idx < 65*128){
        int r = idx >> 7, c = idx & 127;
        float s = 0.f;
        #pragma unroll
        for (int m=0;m<16;m++) s += (W_pe[r*16+m]+b_pe[m]) * W_edge[m*128+c];
        g_Ppe[idx] = s;
    } else if (idx < 65*128 + 2*128){
        int t = idx - 65*128; int r = t >> 7, c = t & 127;
        float s = 0.f;
        #pragma unroll
        for (int m=0;m<16;m++) s += (W_ch[r*16+m]+b_ch[m]) * W_edge[(39+m)*128+c];
        g_Pch[t] = s;
    } else if (idx < 65*128 + 2*128 + 23*128){
        int t = idx - (65*128+2*128); int r = t >> 7, c = t & 127;
        int row = (r < 16) ? (16+r) : (32 + (r-16));
        g_W2r[t] = W_edge[row*128+c];
    }
}

// ---------------- kernel 2: fused top-30 + edge features --------------------
// Filter on pre-sqrt squared sums s (monotone with D). Bound: U = max over
// warps of the 4th-distinct-min of that warp's 32 thread-mins (each warp
// certifies >=4 elements <= its value => >=32 <= U >= K30). Candidates
// (E[C]~70) get exact D = sqrt_rn(s+eps), ranked by (D_bits, j) u64 order.
__global__ void __launch_bounds__(256, 5) k_topk(
        const int* __restrict__ resid, const int* __restrict__ chain,
        float* __restrict__ outIdxF){
    __shared__ unsigned long long sCand[2048];
    __shared__ unsigned long long sWin[32];
    __shared__ unsigned sWA[8];
    __shared__ unsigned sCnt[1];

    int row = blockIdx.x;
    int b   = row >> 11;
    int tid = threadIdx.x;
    int lane = tid & 31, wid = tid >> 5;
    float4 p = g_CaP[row];

    unsigned kreg[8];
    #pragma unroll
    for (int u=0;u<8;u++){
        int j = tid + (u<<8);
        float4 q = g_CaP[(b<<11)+j];
        float dx=q.x-p.x, dy=q.y-p.y, dz=q.z-p.z;
        float s = __fadd_rn(__fadd_rn(__fmul_rn(dx,dx),__fmul_rn(dy,dy)),__fmul_rn(dz,dz));
        kreg[u] = __float_as_uint(s);
    }
    unsigned tmn = kreg[0];
    #pragma unroll
    for (int u=1;u<8;u++) tmn = min(tmn, kreg[u]);
    unsigned v = tmn, m;
    #pragma unroll
    for (int it=0; it<3; it++){
        m = __reduce_min_sync(0xffffffffu, v);
        if (v == m) v = 0xFFFFFFFFu;
    }
    m = __reduce_min_sync(0xffffffffu, v);
    if (lane==0) sWA[wid] = m;
    if (tid==0) sCnt[0] = 0;
    __syncthreads();
    unsigned U = sWA[0];
    #pragma unroll
    for (int i=1;i<8;i++) U = max(U, sWA[i]);

    #pragma unroll
    for (int u=0;u<8;u++){
        bool pred = (kreg[u] <= U);
        unsigned mm = __ballot_sync(0xffffffffu, pred);
        unsigned basew = 0;
        if (lane==0 && mm) basew = atomicAdd(&sCnt[0], __popc(mm));
        basew = __shfl_sync(0xffffffffu, basew, 0);
        if (pred){
            unsigned pos = basew + __popc(mm & ((1u<<lane)-1u));
            sCand[pos] = ((unsigned long long)kreg[u] << 32) | (unsigned)(tid + (u<<8));
        }
    }
    __syncthreads();
    int C  = (int)sCnt[0];
    int C4 = (C + 3) & ~3;

    for (int c2 = tid; c2 < C; c2 += 256){
        unsigned long long ck = sCand[c2];
        float s = __uint_as_float((unsigned)(ck >> 32));
        float D = __fsqrt_rn(__fadd_rn(s, 1e-6f));
        sCand[c2] = ((unsigned long long)__float_as_uint(D) << 32) | (ck & 0xFFFFFFFFull);
    }
    if (tid < C4 - C && C4 <= 2048) sCand[C + tid] = ~0ull;
    __syncthreads();

    unsigned long long selV[8]; unsigned selR[8]; int nsel = 0;
    for (int c2 = tid; c2 < C; c2 += 256){
        unsigned long long ck = sCand[c2];
        unsigned r = 0;
        for (int i=0;i<C4;i+=4){
            r += (sCand[i  ] < ck) ? 1u : 0u;
            r += (sCand[i+1] < ck) ? 1u : 0u;
            r += (sCand[i+2] < ck) ? 1u : 0u;
            r += (sCand[i+3] < ck) ? 1u : 0u;
        }
        if (r < 30u && nsel < 8){ selV[nsel]=ck; selR[nsel]=r; nsel++; }
    }
    for (int i=0;i<nsel;i++) sWin[selR[i]] = selV[i];
    __syncthreads();

    if (tid < TOPK){
        unsigned long long w = sWin[tid];
        unsigned j  = (unsigned)(w & 0xFFFFFFFFu);
        float D = __uint_as_float((unsigned)(w >> 32));
        int e  = row*TOPK + tid;
        outIdxF[e] = (float)j;
        int n  = row;
        int nj = (b<<11) + (int)j;
        int tile = e >> 6, sub = e & 63;
        float* f = g_Feat + (size_t)tile*1536 + sub;
        #pragma unroll
        for (int mm=0;mm<16;mm++){
            float mu = 2.0f + (float)mm*(20.0f/15.0f);
            float t = (D - mu)*0.8f;
            f[mm*64] = expf(-t*t);
        }
        float4 a1=g_E1[n],  a2=g_E2[n],  a3=g_E3[n];
        float4 c1=g_E1[nj], c2v=g_E2[nj], c3=g_E3[nj];
        float4 pj=g_CaP[nj];
        float dx=pj.x-p.x, dy=pj.y-p.y, dz=pj.z-p.z;
        float ux = a1.x*dx + a2.x*dy + a3.x*dz;
        float uy = a1.y*dx + a2.y*dy + a3.y*dz;
        float uz = a1.z*dx + a2.z*dy + a3.z*dz;
        float iu = 1.f/fmaxf(sqrtf(ux*ux+uy*uy+uz*uz), 1e-12f);
        f[16*64]=ux*iu; f[17*64]=uy*iu; f[18*64]=uz*iu;
        float R00=a1.x*c1.x +a1.y*c1.y +a1.z*c1.z;
        float R01=a1.x*c2v.x+a1.y*c2v.y+a1.z*c2v.z;
        float R02=a1.x*c3.x +a1.y*c3.y +a1.z*c3.z;
        float R10=a2.x*c1.x +a2.y*c1.y +a2.z*c1.z;
        float R11=a2.x*c2v.x+a2.y*c2v.y+a2.z*c2v.z;
        float R12=a2.x*c3.x +a2.y*c3.y +a2.z*c3.z;
        float R20=a3.x*c1.x +a3.y*c1.y +a3.z*c1.z;
        float R21=a3.x*c2v.x+a3.y*c2v.y+a3.z*c2v.z;
        float R22=a3.x*c3.x +a3.y*c3.y +a3.z*c3.z;
        float m0 = 0.5f*sqrtf(fabsf(1.f + R00 - R11 - R22));
        float m1 = 0.5f*sqrtf(fabsf(1.f - R00 + R11 - R22));
        float m2 = 0.5f*sqrtf(fabsf(1.f - R00 - R11 + R22));
        float qx = signf_(R21 - R12)*m0;
        float qy = signf_(R02 - R20)*m1;
        float qz = signf_(R10 - R01)*m2;
        float qw = 0.5f*sqrtf(fmaxf(1.f + R00 + R11 + R22, 0.f));
        float iq = 1.f/fmaxf(sqrtf(qx*qx+qy*qy+qz*qz+qw*qw), 1e-12f);
        f[19*64]=qx*iq; f[20*64]=qy*iq; f[21*64]=qz*iq; f[22*64]=qw*iq;
        int off = resid[nj] - resid[n];
        int dcl = min(max(off + 32, 0), 64);
        int sc  = (chain[nj]==chain[n]) ? 0 : 1;
        f[23*64] = __int_as_float(dcl | (sc<<8));
    }
}

// ---------------- kernel 3: node dihedral features + LN (trig-free) ---------
__global__ void k_node(const float* __restrict__ W_node, const float* __restrict__ b_node,
                       const float* __restrict__ gN, const float* __restrict__ bnN,
                       float* __restrict__ outV){
    int gw   = (blockIdx.x*blockDim.x + threadIdx.x) >> 5;
    int lane = threadIdx.x & 31;
    if (gw >= NODES) return;
    int l = gw & 2047;

    float ad0=0.f, ad1=0.f, ad2=0.f;
    if (l >= 1 && l <= LL-3){
        float4 p0=g_CaP[gw-1], p1=g_CaP[gw], p2=g_CaP[gw+1], p3=g_CaP[gw+2];
        float ax=p1.x-p0.x, ay=p1.y-p0.y, az=p1.z-p0.z;
        float bx=p2.x-p1.x, by=p2.y-p1.y, bz=p2.z-p1.z;
        float cx=p3.x-p2.x, cy=p3.y-p2.y, cz=p3.z-p2.z;
        float ia = 1.f/fmaxf(sqrtf(ax*ax+ay*ay+az*az), 1e-12f); ax*=ia; ay*=ia; az*=ia;
        float ib = 1.f/fmaxf(sqrtf(bx*bx+by*by+bz*bz), 1e-12f); bx*=ib; by*=ib; bz*=ib;
        float ic = 1.f/fmaxf(sqrtf(cx*cx+cy*cy+cz*cz), 1e-12f); cx*=ic; cy*=ic; cz*=ic;
        float n2x=ay*bz-az*by, n2y=az*bx-ax*bz, n2z=ax*by-ay*bx;
        float n1x=by*cz-bz*cy, n1y=bz*cx-bx*cz, n1z=bx*cy-by*cx;
        float i2 = 1.f/fmaxf(sqrtf(n2x*n2x+n2y*n2y+n2z*n2z), 1e-12f); n2x*=i2; n2y*=i2; n2z*=i2;
        float i1 = 1.f/fmaxf(sqrtf(n1x*n1x+n1y*n1y+n1z*n1z), 1e-12f); n1x*=i1; n1y*=i1; n1z*=i1;
        float cosA = -(bx*cx+by*cy+bz*cz);
        cosA = fminf(fmaxf(cosA, -1.f+1e-6f), 1.f-1e-6f);
        float cosD = n2x*n1x+n2y*n1y+n2z*n1z;
        cosD = fminf(fmaxf(cosD, -1.f+1e-6f), 1.f-1e-6f);
        float sgn = signf_(ax*n1x+ay*n1y+az*n1z);
        float sA = sqrtf(fmaxf(1.f-cosA*cosA, 0.f));
        float sD = sgn*sqrtf(fmaxf(1.f-cosD*cosD, 0.f));
        ad0 = cosA;
        ad1 = sA*cosD;
        ad2 = sA*sD;
    }
    float h[4];
    #pragma unroll
    for (int i=0;i<4;i++){
        int c = lane + 32*i;
        h[i] = b_node[c] + ad0*W_node[c] + ad1*W_node[128+c] + ad2*W_node[256+c];
    }
    float s = h[0]+h[1]+h[2]+h[3];
    #pragma unroll
    for (int off=16;off;off>>=1) s += __shfl_xor_sync(0xffffffffu, s, off);
    float mu = s * (1.f/128.f);
    float d0=h[0]-mu, d1=h[1]-mu, d2=h[2]-mu, d3=h[3]-mu;
    float ss = d0*d0+d1*d1+d2*d2+d3*d3;
    #pragma unroll
    for (int off=16;off;off>>=1) ss += __shfl_xor_sync(0xffffffffu, ss, off);
    float invr = 1.f/sqrtf(ss*(1.f/128.f) + 1e-5f);
    size_t base = (size_t)gw*128;
    #pragma unroll
    for (int i=0;i<4;i++){
        int c = lane + 32*i;
        outV[base + c] = (h[i]-mu)*invr*gN[c] + bnN[c];
    }
}

// ---------------- kernel 4: edge GEMM (edge-pair f32x2) + LN ----------------
// block 256 threads = 8 warps; warp = 8 edges (4 pairs); lane owns channels [4c,4c+4)
// Mainloop feature loads via 2x LDS.128 (ulonglong2): 3 shared wavefronts/iter.
__global__ void __launch_bounds__(256) k_egemm(
                        const float* __restrict__ b_edge, const float* __restrict__ gE,
                        const float* __restrict__ bnE, float* __restrict__ outE){
    __shared__ float sW[23*128];
    __shared__ float sFt[24][64];
    int tid = threadIdx.x;
    int e0 = blockIdx.x * 64;

    for (int i = tid; i < 23*128; i += 256) sW[i] = g_W2r[i];
    {
        const float4* src = (const float4*)(g_Feat + (size_t)blockIdx.x*1536);
        float4* dst = (float4*)&sFt[0][0];
        dst[tid] = src[tid];
        if (tid < 128) dst[tid+256] = src[tid+256];
    }
    __syncthreads();

    int wrp = tid >> 5, cg = tid & 31;
    int ebase = wrp * 8;
    int c0 = cg * 4;
    float4 bv = *(const float4*)(b_edge + c0);

    unsigned long long acc[4][4];   // [edge-pair][channel] = (edgeA, edgeB)
    #pragma unroll
    for (int pp=0;pp<4;pp++){
        int ea = ebase + 2*pp, eb = ea + 1;
        int ca = __float_as_int(sFt[23][ea]);
        int cb = __float_as_int(sFt[23][eb]);
        float4 peA = *(const float4*)(g_Ppe + (ca&255)*128 + c0);
        float4 pcA = *(const float4*)(g_Pch + (ca>>8)*128 + c0);
        float4 peB = *(const float4*)(g_Ppe + (cb&255)*128 + c0);
        float4 pcB = *(const float4*)(g_Pch + (cb>>8)*128 + c0);
        PACK2(acc[pp][0], bv.x+peA.x+pcA.x, bv.x+peB.x+pcB.x);
        PACK2(acc[pp][1], bv.y+peA.y+pcA.y, bv.y+peB.y+pcB.y);
        PACK2(acc[pp][2], bv.z+peA.z+pcA.z, bv.z+peB.z+pcB.z);
        PACK2(acc[pp][3], bv.w+peA.w+pcA.w, bv.w+peB.w+pcB.w);
    }
    #pragma unroll
    for (int r=0;r<23;r++){
        float4 w4 = *(const float4*)(sW + r*128 + c0);
        unsigned long long w0,w1,w2,w3;
        PACK2(w0, w4.x, w4.x); PACK2(w1, w4.y, w4.y);
        PACK2(w2, w4.z, w4.z); PACK2(w3, w4.w, w4.w);
        ulonglong2 fA = *(const ulonglong2*)(&sFt[r][ebase]);     // pairs 0,1
        ulonglong2 fB = *(const ulonglong2*)(&sFt[r][ebase+4]);   // pairs 2,3
        FMA2(acc[0][0], fA.x, w0, acc[0][0]);
        FMA2(acc[0][1], fA.x, w1, acc[0][1]);
        FMA2(acc[0][2], fA.x, w2, acc[0][2]);
        FMA2(acc[0][3], fA.x, w3, acc[0][3]);
        FMA2(acc[1][0], fA.y, w0, acc[1][0]);
        FMA2(acc[1][1], fA.y, w1, acc[1][1]);
        FMA2(acc[1][2], fA.y, w2, acc[1][2]);
        FMA2(acc[1][3], fA.y, w3, acc[1][3]);
        FMA2(acc[2][0], fB.x, w0, acc[2][0]);
        FMA2(acc[2][1], fB.x, w1, acc[2][1]);
        FMA2(acc[2][2], fB.x, w2, acc[2][2]);
        FMA2(acc[2][3], fB.x, w3, acc[2][3]);
        FMA2(acc[3][0], fB.y, w0, acc[3][0]);
        FMA2(acc[3][1], fB.y, w1, acc[3][1]);
        FMA2(acc[3][2], fB.y, w2, acc[3][2]);
        FMA2(acc[3][3], fB.y, w3, acc[3][3]);
    }
    float4 ge = *(const float4*)(gE + c0);
    float4 be = *(const float4*)(bnE + c0);
    unsigned long long cM;
    PACK2(cM, -0.0078125f, -0.0078125f);   // -1/128
    #pragma unroll
    for (int pp=0;pp<4;pp++){
        unsigned long long s2 = acc[pp][0];
        ADD2(s2, s2, acc[pp][1]);
        ADD2(s2, s2, acc[pp][2]);
        ADD2(s2, s2, acc[pp][3]);
        #pragma unroll
        for (int off=16;off;off>>=1){
            unsigned long long o = __shfl_xor_sync(0xffffffffu, s2, off);
            ADD2(s2, s2, o);
        }
        unsigned long long nmu2; MUL2(nmu2, s2, cM);
        unsigned long long dd[4];
        ADD2(dd[0], acc[pp][0], nmu2);
        ADD2(dd[1], acc[pp][1], nmu2);
        ADD2(dd[2], acc[pp][2], nmu2);
        ADD2(dd[3], acc[pp][3], nmu2);
        unsigned long long ss2; PACK2(ss2, 0.f, 0.f);
        FMA2(ss2, dd[0], dd[0], ss2);
        FMA2(ss2, dd[1], dd[1], ss2);
        FMA2(ss2, dd[2], dd[2], ss2);
        FMA2(ss2, dd[3], dd[3], ss2);
        #pragma unroll
        for (int off=16;off;off>>=1){
            unsigned long long o = __shfl_xor_sync(0xffffffffu, ss2, off);
            ADD2(ss2, ss2, o);
        }
        float ssa, ssb; UNPK2(ssa, ssb, ss2);
        float ira = 1.f/sqrtf(ssa*(1.f/128.f) + 1e-5f);
        float irb = 1.f/sqrtf(ssb*(1.f/128.f) + 1e-5f);
        float d0a,d0b,d1a,d1b,d2a,d2b,d3a,d3b;
        UNPK2(d0a,d0b,dd[0]); UNPK2(d1a,d1b,dd[1]);
        UNPK2(d2a,d2b,dd[2]); UNPK2(d3a,d3b,dd[3]);
        int ea = e0 + ebase + 2*pp;
        float4 oA, oB;
        oA.x = d0a*ira*ge.x + be.x;  oB.x = d0b*irb*ge.x + be.x;
        oA.y = d1a*ira*ge.y + be.y;  oB.y = d1b*irb*ge.y + be.y;
        oA.z = d2a*ira*ge.z + be.z;  oB.z = d2b*irb*ge.z + be.z;
        oA.w = d3a*ira*ge.w + be.w;  oB.w = d3b*irb*ge.w + be.w;
        *(float4*)(outE + (size_t)ea*128 + c0)     = oA;
        *(float4*)(outE + (size_t)(ea+1)*128 + c0) = oB;
    }
}

// ---------------- launch (egemm 4th so ncu captures it) ----------------------
extern "C" void kernel_launch(void* const* d_in, const int* in_sizes, int n_in,
                              void* d_out, int out_size){
    const float* X        = (const float*)d_in[0];
    const int*   resid    = (const int*)  d_in[2];
    const int*   chain    = (const int*)  d_in[3];
    const float* W_pe     = (const float*)d_in[4];
    const float* b_pe     = (const float*)d_in[5];
    const float* W_ch     = (const float*)d_in[6];
    const float* b_ch     = (const float*)d_in[7];
    const float* W_node   = (const float*)d_in[8];
    const float* b_node   = (const float*)d_in[9];
    const float* W_edge   = (const float*)d_in[10];
    const float* b_edge   = (const float*)d_in[11];
    const float* g_nodes  = (const float*)d_in[12];
    const float* bn_nodes = (const float*)d_in[13];
    const float* g_edges  = (const float*)d_in[14];
    const float* bn_edges = (const float*)d_in[15];

    float* out  = (float*)d_out;
    float* outV = out;
    float* outE = out + (size_t)NODES*128;
    float* outI = out + (size_t)NODES*128 + (size_t)NEDGE*128;

    k_prepA<<<32, 256>>>(X);
    k_prepB<<<45, 256>>>(W_pe, b_pe, W_ch, b_ch, W_edge);
    k_topk <<<NODES, 256>>>(resid, chain, outI);
    k_egemm<<<NTILE, 256>>>(b_edge, g_edges, bn_edges, outE);
    k_node <<<NODES/8, 256>>>(W_node, b_node, g_nodes, bn_nodes, outV);
}

// round 16
// speedup vs baseline: 1.0149x; 1.0149x over previous
#include <cuda_runtime.h>
#include <cfloat>
#include <math.h>

#define BB   4
#define LL   2048
#define NODES (BB*LL)            // 8192
#define TOPK 30
#define NEDGE (NODES*TOPK)       // 245760

// ---------------- scratch ----------------------------------------------------
__device__ float4 g_CaP[NODES];
__device__ float4 g_E1[NODES];
__device__ float4 g_E2[NODES];
__device__ float4 g_E3[NODES];
__device__ float  g_Ppe[65*128];           // (W_pe+b_pe) @ W_edge[0:16]
__device__ float  g_Pch[2*128];            // (W_ch+b_ch) @ W_edge[39:55]
__device__ float  g_W2r[23*128];           // W_edge rows [16:39)

__device__ __forceinline__ float signf_(float x){ return (x>0.f)?1.f:((x<0.f)?-1.f:0.f); }

#define FMA2(d,a,b,c) asm("fma.rn.f32x2 %0,%1,%2,%3;" : "=l"(d) : "l"(a), "l"(b), "l"(c))
#define ADD2(d,a,b)   asm("add.rn.f32x2 %0,%1,%2;"    : "=l"(d) : "l"(a), "l"(b))
#define MUL2(d,a,b)   asm("mul.rn.f32x2 %0,%1,%2;"    : "=l"(d) : "l"(a), "l"(b))
#define PACK2(d,lo,hi) asm("mov.b64 %0,{%1,%2};" : "=l"(d) : "f"(lo), "f"(hi))
#define UNPK2(lo,hi,s) asm("mov.b64 {%0,%1},%2;" : "=f"(lo), "=f"(hi) : "l"(s))

// ---------------- kernel 1a: pack Ca + per-node frames ----------------------
__global__ void k_prepA(const float* __restrict__ X){
    int n = blockIdx.x*256 + threadIdx.x;
    const float* p = X + (size_t)n*12;
    float Nx=p[0], Ny=p[1], Nz=p[2];
    float Cx=p[3], Cy=p[4], Cz=p[5];
    float Dx=p[6], Dy=p[7], Dz=p[8];
    g_CaP[n] = make_float4(Cx,Cy,Cz,0.f);
    float v1x=Nx-Cx, v1y=Ny-Cy, v1z=Nz-Cz;
    float v2x=Dx-Cx, v2y=Dy-Cy, v2z=Dz-Cz;
    float n1 = sqrtf(v1x*v1x+v1y*v1y+v1z*v1z);
    float i1 = 1.f/(n1+1e-6f);
    float e1x=v1x*i1, e1y=v1y*i1, e1z=v1z*i1;
    float dv = e1x*v2x+e1y*v2y+e1z*v2z;
    float u2x=v2x-dv*e1x, u2y=v2y-dv*e1y, u2z=v2z-dv*e1z;
    float n2 = sqrtf(u2x*u2x+u2y*u2y+u2z*u2z);
    float i2 = 1.f/(n2+1e-6f);
    float e2x=u2x*i2, e2y=u2y*i2, e2z=u2z*i2;
    g_E1[n] = make_float4(e1x,e1y,e1z,0.f);
    g_E2[n] = make_float4(e2x,e2y,e2z,0.f);
    g_E3[n] = make_float4(e1y*e2z-e1z*e2y, e1z*e2x-e1x*e2z, e1x*e2y-e1y*e2x, 0.f);
}

// ---------------- kernel 1b: projection tables ------------------------------
__global__ void k_prepB(const float* __restrict__ W_pe, const float* __restrict__ b_pe,
                        const float* __restrict__ W_ch, const float* __restrict__ b_ch,
                        const float* __restrict__ W_edge){
    int idx = blockIdx.x*256 + threadIdx.x;
    if (idx < 65*128){
        int r = idx >> 7, c = idx & 127;
        float s = 0.f;
        #pragma unroll
        for (int m=0;m<16;m++) s += (W_pe[r*16+m]+b_pe[m]) * W_edge[m*128+c];
        g_Ppe[idx] = s;
    } else if (idx < 65*128 + 2*128){
        int t = idx - 65*128; int r = t >> 7, c = t & 127;
        float s = 0.f;
        #pragma unroll
        for (int m=0;m<16;m++) s += (W_ch[r*16+m]+b_ch[m]) * W_edge[(39+m)*128+c];
        g_Pch[t] = s;
    } else if (idx < 65*128 + 2*128 + 23*128){
        int t = idx - (65*128+2*128); int r = t >> 7, c = t & 127;
        int row = (r < 16) ? (16+r) : (32 + (r-16));
        g_W2r[t] = W_edge[row*128+c];
    }
}

// ---------------- kernel 2: fully fused top-30 + features + GEMM + LN -------
// Phase 1: thread-min quantile filter + exact rank select (proven R9-R11 path).
// Phase 2: 30 threads compute 23 edge features into shared (slots 30,31 zeroed).
// Phase 3: 8 warps x 4 edges GEMM (f32x2, weights via __ldg, L1-resident) + LN.
__global__ void __launch_bounds__(256, 5) k_topk(
        const int* __restrict__ resid, const int* __restrict__ chain,
        const float* __restrict__ b_edge, const float* __restrict__ gE,
        const float* __restrict__ bnE,
        float* __restrict__ outE, float* __restrict__ outIdxF){
    __shared__ unsigned long long sCand[2048];
    __shared__ unsigned long long sWin[32];
    __shared__ unsigned sWA[8];
    __shared__ unsigned sCnt[1];
    __shared__ __align__(16) float sFt[24][32];   // 8B-reads in phase 3 need alignment

    int row = blockIdx.x;
    int b   = row >> 11;
    int tid = threadIdx.x;
    int lane = tid & 31, wid = tid >> 5;
    float4 p = g_CaP[row];

    unsigned kreg[8];
    #pragma unroll
    for (int u=0;u<8;u++){
        int j = tid + (u<<8);
        float4 q = g_CaP[(b<<11)+j];
        float dx=q.x-p.x, dy=q.y-p.y, dz=q.z-p.z;
        // exact pre-sqrt sum; sqrt deferred to candidates (monotone)
        float s = __fadd_rn(__fadd_rn(__fmul_rn(dx,dx),__fmul_rn(dy,dy)),__fmul_rn(dz,dz));
        kreg[u] = __float_as_uint(s);
    }
    unsigned tmn = kreg[0];
    #pragma unroll
    for (int u=1;u<8;u++) tmn = min(tmn, kreg[u]);
    unsigned v = tmn, m;
    #pragma unroll
    for (int it=0; it<3; it++){
        m = __reduce_min_sync(0xffffffffu, v);
        if (v == m) v = 0xFFFFFFFFu;
    }
    m = __reduce_min_sync(0xffffffffu, v);
    if (lane==0) sWA[wid] = m;
    if (tid==0) sCnt[0] = 0;
    __syncthreads();
    unsigned U = sWA[0];
    #pragma unroll
    for (int i=1;i<8;i++) U = max(U, sWA[i]);

    #pragma unroll
    for (int u=0;u<8;u++){
        bool pred = (kreg[u] <= U);
        unsigned mm = __ballot_sync(0xffffffffu, pred);
        unsigned basew = 0;
        if (lane==0 && mm) basew = atomicAdd(&sCnt[0], __popc(mm));
        basew = __shfl_sync(0xffffffffu, basew, 0);
        if (pred){
            unsigned pos = basew + __popc(mm & ((1u<<lane)-1u));
            sCand[pos] = ((unsigned long long)kreg[u] << 32) | (unsigned)(tid + (u<<8));
        }
    }
    __syncthreads();
    int C  = (int)sCnt[0];
    int C4 = (C + 3) & ~3;

    for (int c2 = tid; c2 < C; c2 += 256){
        unsigned long long ck = sCand[c2];
        float s = __uint_as_float((unsigned)(ck >> 32));
        float D = __fsqrt_rn(__fadd_rn(s, 1e-6f));
        sCand[c2] = ((unsigned long long)__float_as_uint(D) << 32) | (ck & 0xFFFFFFFFull);
    }
    if (tid < C4 - C && C4 <= 2048) sCand[C + tid] = ~0ull;
    __syncthreads();

    unsigned long long selV[8]; unsigned selR[8]; int nsel = 0;
    for (int c2 = tid; c2 < C; c2 += 256){
        unsigned long long ck = sCand[c2];
        unsigned r = 0;
        for (int i=0;i<C4;i+=4){
            r += (sCand[i  ] < ck) ? 1u : 0u;
            r += (sCand[i+1] < ck) ? 1u : 0u;
            r += (sCand[i+2] < ck) ? 1u : 0u;
            r += (sCand[i+3] < ck) ? 1u : 0u;
        }
        if (r < 30u && nsel < 8){ selV[nsel]=ck; selR[nsel]=r; nsel++; }
    }
    for (int i=0;i<nsel;i++) sWin[selR[i]] = selV[i];
    __syncthreads();

    // ---- phase 2: edge features into shared (threads 0-29; 30,31 zero) ----
    if (tid < TOPK){
        unsigned long long w = sWin[tid];
        unsigned j  = (unsigned)(w & 0xFFFFFFFFu);
        float D = __uint_as_float((unsigned)(w >> 32));
        outIdxF[row*TOPK + tid] = (float)j;
        int n  = row;
        int nj = (b<<11) + (int)j;
        #pragma unroll
        for (int mm2=0;mm2<16;mm2++){
            float mu = 2.0f + (float)mm2*(20.0f/15.0f);
            float t = (D - mu)*0.8f;
            sFt[mm2][tid] = expf(-t*t);
        }
        float4 a1=g_E1[n],  a2=g_E2[n],  a3=g_E3[n];
        float4 c1=g_E1[nj], c2v=g_E2[nj], c3=g_E3[nj];
        float4 pj=g_CaP[nj];
        float dx=pj.x-p.x, dy=pj.y-p.y, dz=pj.z-p.z;
        float ux = a1.x*dx + a2.x*dy + a3.x*dz;
        float uy = a1.y*dx + a2.y*dy + a3.y*dz;
        float uz = a1.z*dx + a2.z*dy + a3.z*dz;
        float iu = 1.f/fmaxf(sqrtf(ux*ux+uy*uy+uz*uz), 1e-12f);
        sFt[16][tid]=ux*iu; sFt[17][tid]=uy*iu; sFt[18][tid]=uz*iu;
        float R00=a1.x*c1.x +a1.y*c1.y +a1.z*c1.z;
        float R01=a1.x*c2v.x+a1.y*c2v.y+a1.z*c2v.z;
        float R02=a1.x*c3.x +a1.y*c3.y +a1.z*c3.z;
        float R10=a2.x*c1.x +a2.y*c1.y +a2.z*c1.z;
        float R11=a2.x*c2v.x+a2.y*c2v.y+a2.z*c2v.z;
        float R12=a2.x*c3.x +a2.y*c3.y +a2.z*c3.z;
        float R20=a3.x*c1.x +a3.y*c1.y +a3.z*c1.z;
        float R21=a3.x*c2v.x+a3.y*c2v.y+a3.z*c2v.z;
        float R22=a3.x*c3.x +a3.y*c3.y +a3.z*c3.z;
        float m0 = 0.5f*sqrtf(fabsf(1.f + R00 - R11 - R22));
        float m1 = 0.5f*sqrtf(fabsf(1.f - R00 + R11 - R22));
        float m2 = 0.5f*sqrtf(fabsf(1.f - R00 - R11 + R22));
        float qx = signf_(R21 - R12)*m0;
        float qy = signf_(R02 - R20)*m1;
        float qz = signf_(R10 - R01)*m2;
        float qw = 0.5f*sqrtf(fmaxf(1.f + R00 + R11 + R22, 0.f));
        float iq = 1.f/fmaxf(sqrtf(qx*qx+qy*qy+qz*qz+qw*qw), 1e-12f);
        sFt[19][tid]=qx*iq; sFt[20][tid]=qy*iq; sFt[21][tid]=qz*iq; sFt[22][tid]=qw*iq;
        int off = resid[nj] - resid[row];
        int dcl = min(max(off + 32, 0), 64);
        int sc  = (chain[nj]==chain[row]) ? 0 : 1;
        sFt[23][tid] = __int_as_float(dcl | (sc<<8));
    } else if (tid < 32){
        #pragma unroll
        for (int r2=0;r2<24;r2++) sFt[r2][tid] = 0.f;   // class 0 -> valid row
    }
    __syncthreads();

    // ---- phase 3: GEMM + LN. 8 warps x 4 edges (2 f32x2 pairs); lane: 4 ch --
    {
        int ebase = wid * 4;            // edges [ebase, ebase+4)
        int c0 = lane * 4;
        float4 bv = *(const float4*)(b_edge + c0);
        float4 ge = *(const float4*)(gE + c0);
        float4 be = *(const float4*)(bnE + c0);

        unsigned long long acc[2][4];
        #pragma unroll
        for (int pp=0;pp<2;pp++){
            int ea = ebase + 2*pp, eb = ea + 1;
            int ca = __float_as_int(sFt[23][ea]);
            int cb = __float_as_int(sFt[23][eb]);
            float4 peA = *(const float4*)(g_Ppe + (ca&255)*128 + c0);
            float4 pcA = *(const float4*)(g_Pch + (ca>>8)*128 + c0);
            float4 peB = *(const float4*)(g_Ppe + (cb&255)*128 + c0);
            float4 pcB = *(const float4*)(g_Pch + (cb>>8)*128 + c0);
            PACK2(acc[pp][0], bv.x+peA.x+pcA.x, bv.x+peB.x+pcB.x);
            PACK2(acc[pp][1], bv.y+peA.y+pcA.y, bv.y+peB.y+pcB.y);
            PACK2(acc[pp][2], bv.z+peA.z+pcA.z, bv.z+peB.z+pcB.z);
            PACK2(acc[pp][3], bv.w+peA.w+pcA.w, bv.w+peB.w+pcB.w);
        }
        #pragma unroll
        for (int r=0;r<23;r++){
            float4 w4 = __ldg((const float4*)(g_W2r + r*128 + c0));
            unsigned long long w0,w1,w2,w3;
            PACK2(w0, w4.x, w4.x); PACK2(w1, w4.y, w4.y);
            PACK2(w2, w4.z, w4.z); PACK2(w3, w4.w, w4.w);
            unsigned long long fA = *(const unsigned long long*)(&sFt[r][ebase]);
            unsigned long long fB = *(const unsigned long long*)(&sFt[r][ebase+2]);
            FMA2(acc[0][0], fA, w0, acc[0][0]);
            FMA2(acc[0][1], fA, w1, acc[0][1]);
            FMA2(acc[0][2], fA, w2, acc[0][2]);
            FMA2(acc[0][3], fA, w3, acc[0][3]);
            FMA2(acc[1][0], fB, w0, acc[1][0]);
            FMA2(acc[1][1], fB, w1, acc[1][1]);
            FMA2(acc[1][2], fB, w2, acc[1][2]);
            FMA2(acc[1][3], fB, w3, acc[1][3]);
        }
        unsigned long long cM;
        PACK2(cM, -0.0078125f, -0.0078125f);   // -1/128
        #pragma unroll
        for (int pp=0;pp<2;pp++){
            unsigned long long s2 = acc[pp][0];
            ADD2(s2, s2, acc[pp][1]);
            ADD2(s2, s2, acc[pp][2]);
            ADD2(s2, s2, acc[pp][3]);
            #pragma unroll
            for (int off=16;off;off>>=1){
                unsigned long long o = __shfl_xor_sync(0xffffffffu, s2, off);
                ADD2(s2, s2, o);
            }
            unsigned long long nmu2; MUL2(nmu2, s2, cM);
            unsigned long long dd[4];
            ADD2(dd[0], acc[pp][0], nmu2);
            ADD2(dd[1], acc[pp][1], nmu2);
            ADD2(dd[2], acc[pp][2], nmu2);
            ADD2(dd[3], acc[pp][3], nmu2);
            unsigned long long ss2; PACK2(ss2, 0.f, 0.f);
            FMA2(ss2, dd[0], dd[0], ss2);
            FMA2(ss2, dd[1], dd[1], ss2);
            FMA2(ss2, dd[2], dd[2], ss2);
            FMA2(ss2, dd[3], dd[3], ss2);
            #pragma unroll
            for (int off=16;off;off>>=1){
                unsigned long long o = __shfl_xor_sync(0xffffffffu, ss2, off);
                ADD2(ss2, ss2, o);
            }
            float ssa, ssb; UNPK2(ssa, ssb, ss2);
            float ira = 1.f/sqrtf(ssa*(1.f/128.f) + 1e-5f);
            float irb = 1.f/sqrtf(ssb*(1.f/128.f) + 1e-5f);
            float d0a,d0b,d1a,d1b,d2a,d2b,d3a,d3b;
            UNPK2(d0a,d0b,dd[0]); UNPK2(d1a,d1b,dd[1]);
            UNPK2(d2a,d2b,dd[2]); UNPK2(d3a,d3b,dd[3]);
            int ea = ebase + 2*pp;
            if (ea < TOPK){
                float4 oA;
                oA.x = d0a*ira*ge.x + be.x;
                oA.y = d1a*ira*ge.y + be.y;
                oA.z = d2a*ira*ge.z + be.z;
                oA.w = d3a*ira*ge.w + be.w;
                *(float4*)(outE + (size_t)(row*TOPK + ea)*128 + c0) = oA;
            }
            if (ea + 1 < TOPK){
                float4 oB;
                oB.x = d0b*irb*ge.x + be.x;
                oB.y = d1b*irb*ge.y + be.y;
                oB.z = d2b*irb*ge.z + be.z;
                oB.w = d3b*irb*ge.w + be.w;
                *(float4*)(outE + (size_t)(row*TOPK + ea + 1)*128 + c0) = oB;
            }
        }
    }
}

// ---------------- kernel 3: node dihedral features + LN (trig-free) ---------
__global__ void k_node(const float* __restrict__ W_node, const float* __restrict__ b_node,
                       const float* __restrict__ gN, const float* __restrict__ bnN,
                       float* __restrict__ outV){
    int gw   = (blockIdx.x*blockDim.x + threadIdx.x) >> 5;
    int lane = threadIdx.x & 31;
    if (gw >= NODES) return;
    int l = gw & 2047;

    float ad0=0.f, ad1=0.f, ad2=0.f;
    if (l >= 1 && l <= LL-3){
        float4 p0=g_CaP[gw-1], p1=g_CaP[gw], p2=g_CaP[gw+1], p3=g_CaP[gw+2];
        float ax=p1.x-p0.x, ay=p1.y-p0.y, az=p1.z-p0.z;
        float bx=p2.x-p1.x, by=p2.y-p1.y, bz=p2.z-p1.z;
        float cx=p3.x-p2.x, cy=p3.y-p2.y, cz=p3.z-p2.z;
        float ia = 1.f/fmaxf(sqrtf(ax*ax+ay*ay+az*az), 1e-12f); ax*=ia; ay*=ia; az*=ia;
        float ib = 1.f/fmaxf(sqrtf(bx*bx+by*by+bz*bz), 1e-12f); bx*=ib; by*=ib; bz*=ib;
        float ic = 1.f/fmaxf(sqrtf(cx*cx+cy*cy+cz*cz), 1e-12f); cx*=ic; cy*=ic; cz*=ic;
        float n2x=ay*bz-az*by, n2y=az*bx-ax*bz, n2z=ax*by-ay*bx;
        float n1x=by*cz-bz*cy, n1y=bz*cx-bx*cz, n1z=bx*cy-by*cx;
        float i2 = 1.f/fmaxf(sqrtf(n2x*n2x+n2y*n2y+n2z*n2z), 1e-12f); n2x*=i2; n2y*=i2; n2z*=i2;
        float i1 = 1.f/fmaxf(sqrtf(n1x*n1x+n1y*n1y+n1z*n1z), 1e-12f); n1x*=i1; n1y*=i1; n1z*=i1;
        float cosA = -(bx*cx+by*cy+bz*cz);
        cosA = fminf(fmaxf(cosA, -1.f+1e-6f), 1.f-1e-6f);
        float cosD = n2x*n1x+n2y*n1y+n2z*n1z;
        cosD = fminf(fmaxf(cosD, -1.f+1e-6f), 1.f-1e-6f);
        float sgn = signf_(ax*n1x+ay*n1y+az*n1z);
        float sA = sqrtf(fmaxf(1.f-cosA*cosA, 0.f));
        float sD = sgn*sqrtf(fmaxf(1.f-cosD*cosD, 0.f));
        ad0 = cosA;
        ad1 = sA*cosD;
        ad2 = sA*sD;
    }
    float h[4];
    #pragma unroll
    for (int i=0;i<4;i++){
        int c = lane + 32*i;
        h[i] = b_node[c] + ad0*W_node[c] + ad1*W_node[128+c] + ad2*W_node[256+c];
    }
    float s = h[0]+h[1]+h[2]+h[3];
    #pragma unroll
    for (int off=16;off;off>>=1) s += __shfl_xor_sync(0xffffffffu, s, off);
    float mu = s * (1.f/128.f);
    float d0=h[0]-mu, d1=h[1]-mu, d2=h[2]-mu, d3=h[3]-mu;
    float ss = d0*d0+d1*d1+d2*d2+d3*d3;
    #pragma unroll
    for (int off=16;off;off>>=1) ss += __shfl_xor_sync(0xffffffffu, ss, off);
    float invr = 1.f/sqrtf(ss*(1.f/128.f) + 1e-5f);
    size_t base = (size_t)gw*128;
    #pragma unroll
    for (int i=0;i<4;i++){
        int c = lane + 32*i;
        outV[base + c] = (h[i]-mu)*invr*gN[c] + bnN[c];
    }
}

// ---------------- launch ------------------------------------------------------
extern "C" void kernel_launch(void* const* d_in, const int* in_sizes, int n_in,
                              void* d_out, int out_size){
    const float* X        = (const float*)d_in[0];
    const int*   resid    = (const int*)  d_in[2];
    const int*   chain    = (const int*)  d_in[3];
    const float* W_pe     = (const float*)d_in[4];
    const float* b_pe     = (const float*)d_in[5];
    const float* W_ch     = (const float*)d_in[6];
    const float* b_ch     = (const float*)d_in[7];
    const float* W_node   = (const float*)d_in[8];
    const float* b_node   = (const float*)d_in[9];
    const float* W_edge   = (const float*)d_in[10];
    const float* b_edge   = (const float*)d_in[11];
    const float* g_nodes  = (const float*)d_in[12];
    const float* bn_nodes = (const float*)d_in[13];
    const float* g_edges  = (const float*)d_in[14];
    const float* bn_edges = (const float*)d_in[15];

    float* out  = (float*)d_out;
    float* outV = out;
    float* outE = out + (size_t)NODES*128;
    float* outI = out + (size_t)NODES*128 + (size_t)NEDGE*128;

    k_prepA<<<32, 256>>>(X);
    k_prepB<<<45, 256>>>(W_pe, b_pe, W_ch, b_ch, W_edge);
    k_topk <<<NODES, 256>>>(resid, chain, b_edge, g_edges, bn_edges, outE, outI);
    k_node <<<NODES/8, 256>>>(W_node, b_node, g_nodes, bn_nodes, outV);
}

// round 17
// speedup vs baseline: 1.0172x; 1.0022x over previous
#include <cuda_runtime.h>
#include <cfloat>
#include <math.h>

#define BB   4
#define LL   2048
#define NODES (BB*LL)            // 8192
#define TOPK 30
#define NEDGE (NODES*TOPK)       // 245760

// ---------------- scratch ----------------------------------------------------
__device__ float4 g_CaP[NODES];
__device__ float4 g_E1[NODES];
__device__ float4 g_E2[NODES];
__device__ float4 g_E3[NODES];
__device__ float  g_Ppe[65*128];           // (W_pe+b_pe) @ W_edge[0:16]
__device__ float  g_Pch[2*128];            // (W_ch+b_ch) @ W_edge[39:55]
__device__ float  g_W2r[23*128];           // W_edge rows [16:39)

__device__ __forceinline__ float signf_(float x){ return (x>0.f)?1.f:((x<0.f)?-1.f:0.f); }

#define FMA2(d,a,b,c) asm("fma.rn.f32x2 %0,%1,%2,%3;" : "=l"(d) : "l"(a), "l"(b), "l"(c))
#define ADD2(d,a,b)   asm("add.rn.f32x2 %0,%1,%2;"    : "=l"(d) : "l"(a), "l"(b))
#define MUL2(d,a,b)   asm("mul.rn.f32x2 %0,%1,%2;"    : "=l"(d) : "l"(a), "l"(b))
#define PACK2(d,lo,hi) asm("mov.b64 %0,{%1,%2};" : "=l"(d) : "f"(lo), "f"(hi))
#define UNPK2(lo,hi,s) asm("mov.b64 {%0,%1},%2;" : "=f"(lo), "=f"(hi) : "l"(s))

// ---------------- kernel 1a: pack Ca + per-node frames ----------------------
__global__ void k_prepA(const float* __restrict__ X){
    int n = blockIdx.x*256 + threadIdx.x;
    const float* p = X + (size_t)n*12;
    float Nx=p[0], Ny=p[1], Nz=p[2];
    float Cx=p[3], Cy=p[4], Cz=p[5];
    float Dx=p[6], Dy=p[7], Dz=p[8];
    g_CaP[n] = make_float4(Cx,Cy,Cz,0.f);
    float v1x=Nx-Cx, v1y=Ny-Cy, v1z=Nz-Cz;
    float v2x=Dx-Cx, v2y=Dy-Cy, v2z=Dz-Cz;
    float n1 = sqrtf(v1x*v1x+v1y*v1y+v1z*v1z);
    float i1 = 1.f/(n1+1e-6f);
    float e1x=v1x*i1, e1y=v1y*i1, e1z=v1z*i1;
    float dv = e1x*v2x+e1y*v2y+e1z*v2z;
    float u2x=v2x-dv*e1x, u2y=v2y-dv*e1y, u2z=v2z-dv*e1z;
    float n2 = sqrtf(u2x*u2x+u2y*u2y+u2z*u2z);
    float i2 = 1.f/(n2+1e-6f);
    float e2x=u2x*i2, e2y=u2y*i2, e2z=u2z*i2;
    g_E1[n] = make_float4(e1x,e1y,e1z,0.f);
    g_E2[n] = make_float4(e2x,e2y,e2z,0.f);
    g_E3[n] = make_float4(e1y*e2z-e1z*e2y, e1z*e2x-e1x*e2z, e1x*e2y-e1y*e2x, 0.f);
}

// ---------------- kernel 1b: projection tables ------------------------------
__global__ void k_prepB(const float* __restrict__ W_pe, const float* __restrict__ b_pe,
                        const float* __restrict__ W_ch, const float* __restrict__ b_ch,
                        const float* __restrict__ W_edge){
    int idx = blockIdx.x*256 + threadIdx.x;
    if (idx < 65*128){
        int r = idx >> 7, c = idx & 127;
        float s = 0.f;
        #pragma unroll
        for (int m=0;m<16;m++) s += (W_pe[r*16+m]+b_pe[m]) * W_edge[m*128+c];
        g_Ppe[idx] = s;
    } else if (idx < 65*128 + 2*128){
        int t = idx - 65*128; int r = t >> 7, c = t & 127;
        float s = 0.f;
        #pragma unroll
        for (int m=0;m<16;m++) s += (W_ch[r*16+m]+b_ch[m]) * W_edge[(39+m)*128+c];
        g_Pch[t] = s;
    } else if (idx < 65*128 + 2*128 + 23*128){
        int t = idx - (65*128+2*128); int r = t >> 7, c = t & 127;
        int row = (r < 16) ? (16+r) : (32 + (r-16));
        g_W2r[t] = W_edge[row*128+c];
    }
}

// ---------------- kernel 2: fully fused top-30 + features + GEMM + LN -------
// Phase 1: thread-min quantile filter + exact rank select (proven R9-R11 path).
// Phase 2: 30 threads compute 23 edge features into shared (slots 30,31 zeroed).
// Phase 3: 8 warps x 4 edges GEMM (f32x2, weights via __ldg, L1-resident) + LN.
__global__ void __launch_bounds__(256, 5) k_topk(
        const int* __restrict__ resid, const int* __restrict__ chain,
        const float* __restrict__ b_edge, const float* __restrict__ gE,
        const float* __restrict__ bnE,
        float* __restrict__ outE, float* __restrict__ outIdxF){
    __shared__ unsigned long long sCand[2048];
    __shared__ unsigned long long sWin[32];
    __shared__ unsigned sWA[8];
    __shared__ unsigned sCnt[1];
    __shared__ __align__(16) float sFt[24][32];   // 8B-reads in phase 3 need alignment

    int row = blockIdx.x;
    int b   = row >> 11;
    int tid = threadIdx.x;
    int lane = tid & 31, wid = tid >> 5;
    float4 p = g_CaP[row];

    unsigned kreg[8];
    #pragma unroll
    for (int u=0;u<8;u++){
        int j = tid + (u<<8);
        float4 q = g_CaP[(b<<11)+j];
        float dx=q.x-p.x, dy=q.y-p.y, dz=q.z-p.z;
        // exact pre-sqrt sum; sqrt deferred to candidates (monotone)
        float s = __fadd_rn(__fadd_rn(__fmul_rn(dx,dx),__fmul_rn(dy,dy)),__fmul_rn(dz,dz));
        kreg[u] = __float_as_uint(s);
    }
    unsigned tmn = kreg[0];
    #pragma unroll
    for (int u=1;u<8;u++) tmn = min(tmn, kreg[u]);
    unsigned v = tmn, m;
    #pragma unroll
    for (int it=0; it<3; it++){
        m = __reduce_min_sync(0xffffffffu, v);
        if (v == m) v = 0xFFFFFFFFu;
    }
    m = __reduce_min_sync(0xffffffffu, v);
    if (lane==0) sWA[wid] = m;
    if (tid==0) sCnt[0] = 0;
    __syncthreads();
    unsigned U = sWA[0];
    #pragma unroll
    for (int i=1;i<8;i++) U = max(U, sWA[i]);

    #pragma unroll
    for (int u=0;u<8;u++){
        bool pred = (kreg[u] <= U);
        unsigned mm = __ballot_sync(0xffffffffu, pred);
        unsigned basew = 0;
        if (lane==0 && mm) basew = atomicAdd(&sCnt[0], __popc(mm));
        basew = __shfl_sync(0xffffffffu, basew, 0);
        if (pred){
            unsigned pos = basew + __popc(mm & ((1u<<lane)-1u));
            sCand[pos] = ((unsigned long long)kreg[u] << 32) | (unsigned)(tid + (u<<8));
        }
    }
    __syncthreads();
    int C  = (int)sCnt[0];
    int C4 = (C + 3) & ~3;

    for (int c2 = tid; c2 < C; c2 += 256){
        unsigned long long ck = sCand[c2];
        float s = __uint_as_float((unsigned)(ck >> 32));
        float D = __fsqrt_rn(__fadd_rn(s, 1e-6f));
        sCand[c2] = ((unsigned long long)__float_as_uint(D) << 32) | (ck & 0xFFFFFFFFull);
    }
    if (tid < C4 - C && C4 <= 2048) sCand[C + tid] = ~0ull;
    __syncthreads();

    unsigned long long selV[8]; unsigned selR[8]; int nsel = 0;
    for (int c2 = tid; c2 < C; c2 += 256){
        unsigned long long ck = sCand[c2];
        unsigned r = 0;
        for (int i=0;i<C4;i+=4){
            r += (sCand[i  ] < ck) ? 1u : 0u;
            r += (sCand[i+1] < ck) ? 1u : 0u;
            r += (sCand[i+2] < ck) ? 1u : 0u;
            r += (sCand[i+3] < ck) ? 1u : 0u;
        }
        if (r < 30u && nsel < 8){ selV[nsel]=ck; selR[nsel]=r; nsel++; }
    }
    for (int i=0;i<nsel;i++) sWin[selR[i]] = selV[i];
    __syncthreads();

    // ---- phase 2: edge features into shared (threads 0-29; 30,31 zero) ----
    if (tid < TOPK){
        unsigned long long w = sWin[tid];
        unsigned j  = (unsigned)(w & 0xFFFFFFFFu);
        float D = __uint_as_float((unsigned)(w >> 32));
        outIdxF[row*TOPK + tid] = (float)j;
        int n  = row;
        int nj = (b<<11) + (int)j;
        #pragma unroll
        for (int mm2=0;mm2<16;mm2++){
            float mu = 2.0f + (float)mm2*(20.0f/15.0f);
            float t = (D - mu)*0.8f;
            sFt[mm2][tid] = expf(-t*t);
        }
        float4 a1=g_E1[n],  a2=g_E2[n],  a3=g_E3[n];
        float4 c1=g_E1[nj], c2v=g_E2[nj], c3=g_E3[nj];
        float4 pj=g_CaP[nj];
        float dx=pj.x-p.x, dy=pj.y-p.y, dz=pj.z-p.z;
        float ux = a1.x*dx + a2.x*dy + a3.x*dz;
        float uy = a1.y*dx + a2.y*dy + a3.y*dz;
        float uz = a1.z*dx + a2.z*dy + a3.z*dz;
        float iu = 1.f/fmaxf(sqrtf(ux*ux+uy*uy+uz*uz), 1e-12f);
        sFt[16][tid]=ux*iu; sFt[17][tid]=uy*iu; sFt[18][tid]=uz*iu;
        float R00=a1.x*c1.x +a1.y*c1.y +a1.z*c1.z;
        float R01=a1.x*c2v.x+a1.y*c2v.y+a1.z*c2v.z;
        float R02=a1.x*c3.x +a1.y*c3.y +a1.z*c3.z;
        float R10=a2.x*c1.x +a2.y*c1.y +a2.z*c1.z;
        float R11=a2.x*c2v.x+a2.y*c2v.y+a2.z*c2v.z;
        float R12=a2.x*c3.x +a2.y*c3.y +a2.z*c3.z;
        float R20=a3.x*c1.x +a3.y*c1.y +a3.z*c1.z;
        float R21=a3.x*c2v.x+a3.y*c2v.y+a3.z*c2v.z;
        float R22=a3.x*c3.x +a3.y*c3.y +a3.z*c3.z;
        float m0 = 0.5f*sqrtf(fabsf(1.f + R00 - R11 - R22));
        float m1 = 0.5f*sqrtf(fabsf(1.f - R00 + R11 - R22));
        float m2 = 0.5f*sqrtf(fabsf(1.f - R00 - R11 + R22));
        float qx = signf_(R21 - R12)*m0;
        float qy = signf_(R02 - R20)*m1;
        float qz = signf_(R10 - R01)*m2;
        float qw = 0.5f*sqrtf(fmaxf(1.f + R00 + R11 + R22, 0.f));
        float iq = 1.f/fmaxf(sqrtf(qx*qx+qy*qy+qz*qz+qw*qw), 1e-12f);
        sFt[19][tid]=qx*iq; sFt[20][tid]=qy*iq; sFt[21][tid]=qz*iq; sFt[22][tid]=qw*iq;
        int off = resid[nj] - resid[row];
        int dcl = min(max(off + 32, 0), 64);
        int sc  = (chain[nj]==chain[row]) ? 0 : 1;
        sFt[23][tid] = __int_as_float(dcl | (sc<<8));
    } else if (tid < 32){
        #pragma unroll
        for (int r2=0;r2<24;r2++) sFt[r2][tid] = 0.f;   // class 0 -> valid row
    }
    __syncthreads();

    // ---- phase 3: GEMM + LN. 8 warps x 4 edges (2 f32x2 pairs); lane: 4 ch --
    {
        int ebase = wid * 4;            // edges [ebase, ebase+4)
        int c0 = lane * 4;
        float4 bv = *(const float4*)(b_edge + c0);
        float4 ge = *(const float4*)(gE + c0);
        float4 be = *(const float4*)(bnE + c0);

        unsigned long long acc[2][4];
        #pragma unroll
        for (int pp=0;pp<2;pp++){
            int ea = ebase + 2*pp, eb = ea + 1;
            int ca = __float_as_int(sFt[23][ea]);
            int cb = __float_as_int(sFt[23][eb]);
            float4 peA = *(const float4*)(g_Ppe + (ca&255)*128 + c0);
            float4 pcA = *(const float4*)(g_Pch + (ca>>8)*128 + c0);
            float4 peB = *(const float4*)(g_Ppe + (cb&255)*128 + c0);
            float4 pcB = *(const float4*)(g_Pch + (cb>>8)*128 + c0);
            PACK2(acc[pp][0], bv.x+peA.x+pcA.x, bv.x+peB.x+pcB.x);
            PACK2(acc[pp][1], bv.y+peA.y+pcA.y, bv.y+peB.y+pcB.y);
            PACK2(acc[pp][2], bv.z+peA.z+pcA.z, bv.z+peB.z+pcB.z);
            PACK2(acc[pp][3], bv.w+peA.w+pcA.w, bv.w+peB.w+pcB.w);
        }
        #pragma unroll
        for (int r=0;r<23;r++){
            float4 w4 = __ldg((const float4*)(g_W2r + r*128 + c0));
            unsigned long long w0,w1,w2,w3;
            PACK2(w0, w4.x, w4.x); PACK2(w1, w4.y, w4.y);
            PACK2(w2, w4.z, w4.z); PACK2(w3, w4.w, w4.w);
            unsigned long long fA = *(const unsigned long long*)(&sFt[r][ebase]);
            unsigned long long fB = *(const unsigned long long*)(&sFt[r][ebase+2]);
            FMA2(acc[0][0], fA, w0, acc[0][0]);
            FMA2(acc[0][1], fA, w1, acc[0][1]);
            FMA2(acc[0][2], fA, w2, acc[0][2]);
            FMA2(acc[0][3], fA, w3, acc[0][3]);
            FMA2(acc[1][0], fB, w0, acc[1][0]);
            FMA2(acc[1][1], fB, w1, acc[1][1]);
            FMA2(acc[1][2], fB, w2, acc[1][2]);
            FMA2(acc[1][3], fB, w3, acc[1][3]);
        }
        unsigned long long cM;
        PACK2(cM, -0.0078125f, -0.0078125f);   // -1/128
        #pragma unroll
        for (int pp=0;pp<2;pp++){
            unsigned long long s2 = acc[pp][0];
            ADD2(s2, s2, acc[pp][1]);
            ADD2(s2, s2, acc[pp][2]);
            ADD2(s2, s2, acc[pp][3]);
            #pragma unroll
            for (int off=16;off;off>>=1){
                unsigned long long o = __shfl_xor_sync(0xffffffffu, s2, off);
                ADD2(s2, s2, o);
            }
            unsigned long long nmu2; MUL2(nmu2, s2, cM);
            unsigned long long dd[4];
            ADD2(dd[0], acc[pp][0], nmu2);
            ADD2(dd[1], acc[pp][1], nmu2);
            ADD2(dd[2], acc[pp][2], nmu2);
            ADD2(dd[3], acc[pp][3], nmu2);
            unsigned long long ss2; PACK2(ss2, 0.f, 0.f);
            FMA2(ss2, dd[0], dd[0], ss2);
            FMA2(ss2, dd[1], dd[1], ss2);
            FMA2(ss2, dd[2], dd[2], ss2);
            FMA2(ss2, dd[3], dd[3], ss2);
            #pragma unroll
            for (int off=16;off;off>>=1){
                unsigned long long o = __shfl_xor_sync(0xffffffffu, ss2, off);
                ADD2(ss2, ss2, o);
            }
            float ssa, ssb; UNPK2(ssa, ssb, ss2);
            float ira = 1.f/sqrtf(ssa*(1.f/128.f) + 1e-5f);
            float irb = 1.f/sqrtf(ssb*(1.f/128.f) + 1e-5f);
            float d0a,d0b,d1a,d1b,d2a,d2b,d3a,d3b;
            UNPK2(d0a,d0b,dd[0]); UNPK2(d1a,d1b,dd[1]);
            UNPK2(d2a,d2b,dd[2]); UNPK2(d3a,d3b,dd[3]);
            int ea = ebase + 2*pp;
            if (ea < TOPK){
                float4 oA;
                oA.x = d0a*ira*ge.x + be.x;
                oA.y = d1a*ira*ge.y + be.y;
                oA.z = d2a*ira*ge.z + be.z;
                oA.w = d3a*ira*ge.w + be.w;
                *(float4*)(outE + (size_t)(row*TOPK + ea)*128 + c0) = oA;
            }
            if (ea + 1 < TOPK){
                float4 oB;
                oB.x = d0b*irb*ge.x + be.x;
                oB.y = d1b*irb*ge.y + be.y;
                oB.z = d2b*irb*ge.z + be.z;
                oB.w = d3b*irb*ge.w + be.w;
                *(float4*)(outE + (size_t)(row*TOPK + ea + 1)*128 + c0) = oB;
            }
        }
    }
}

// ---------------- kernel 3: node dihedral features + LN (trig-free) ---------
__global__ void k_node(const float* __restrict__ W_node, const float* __restrict__ b_node,
                       const float* __restrict__ gN, const float* __restrict__ bnN,
                       float* __restrict__ outV){
    int gw   = (blockIdx.x*blockDim.x + threadIdx.x) >> 5;
    int lane = threadIdx.x & 31;
    if (gw >= NODES) return;
    int l = gw & 2047;

    float ad0=0.f, ad1=0.f, ad2=0.f;
    if (l >= 1 && l <= LL-3){
        float4 p0=g_CaP[gw-1], p1=g_CaP[gw], p2=g_CaP[gw+1], p3=g_CaP[gw+2];
        float ax=p1.x-p0.x, ay=p1.y-p0.y, az=p1.z-p0.z;
        float bx=p2.x-p1.x, by=p2.y-p1.y, bz=p2.z-p1.z;
        float cx=p3.x-p2.x, cy=p3.y-p2.y, cz=p3.z-p2.z;
        float ia = 1.f/fmaxf(sqrtf(ax*ax+ay*ay+az*az), 1e-12f); ax*=ia; ay*=ia; az*=ia;
        float ib = 1.f/fmaxf(sqrtf(bx*bx+by*by+bz*bz), 1e-12f); bx*=ib; by*=ib; bz*=ib;
        float ic = 1.f/fmaxf(sqrtf(cx*cx+cy*cy+cz*cz), 1e-12f); cx*=ic; cy*=ic; cz*=ic;
        float n2x=ay*bz-az*by, n2y=az*bx-ax*bz, n2z=ax*by-ay*bx;
        float n1x=by*cz-bz*cy, n1y=bz*cx-bx*cz, n1z=bx*cy-by*cx;
        float i2 = 1.f/fmaxf(sqrtf(n2x*n2x+n2y*n2y+n2z*n2z), 1e-12f); n2x*=i2; n2y*=i2; n2z*=i2;
        float i1 = 1.f/fmaxf(sqrtf(n1x*n1x+n1y*n1y+n1z*n1z), 1e-12f); n1x*=i1; n1y*=i1; n1z*=i1;
        float cosA = -(bx*cx+by*cy+bz*cz);
        cosA = fminf(fmaxf(cosA, -1.f+1e-6f), 1.f-1e-6f);
        float cosD = n2x*n1x+n2y*n1y+n2z*n1z;
        cosD = fminf(fmaxf(cosD, -1.f+1e-6f), 1.f-1e-6f);
        float sgn = signf_(ax*n1x+ay*n1y+az*n1z);
        float sA = sqrtf(fmaxf(1.f-cosA*cosA, 0.f));
        float sD = sgn*sqrtf(fmaxf(1.f-cosD*cosD, 0.f));
        ad0 = cosA;
        ad1 = sA*cosD;
        ad2 = sA*sD;
    }
    float h[4];
    #pragma unroll
    for (int i=0;i<4;i++){
        int c = lane + 32*i;
        h[i] = b_node[c] + ad0*W_node[c] + ad1*W_node[128+c] + ad2*W_node[256+c];
    }
    float s = h[0]+h[1]+h[2]+h[3];
    #pragma unroll
    for (int off=16;off;off>>=1) s += __shfl_xor_sync(0xffffffffu, s, off);
    float mu = s * (1.f/128.f);
    float d0=h[0]-mu, d1=h[1]-mu, d2=h[2]-mu, d3=h[3]-mu;
    float ss = d0*d0+d1*d1+d2*d2+d3*d3;
    #pragma unroll
    for (int off=16;off;off>>=1) ss += __shfl_xor_sync(0xffffffffu, ss, off);
    float invr = 1.f/sqrtf(ss*(1.f/128.f) + 1e-5f);
    size_t base = (size_t)gw*128;
    #pragma unroll
    for (int i=0;i<4;i++){
        int c = lane + 32*i;
        outV[base + c] = (h[i]-mu)*invr*gN[c] + bnN[c];
    }
}

// ---------------- launch ------------------------------------------------------
extern "C" void kernel_launch(void* const* d_in, const int* in_sizes, int n_in,
                              void* d_out, int out_size){
    const float* X        = (const float*)d_in[0];
    const int*   resid    = (const int*)  d_in[2];
    const int*   chain    = (const int*)  d_in[3];
    const float* W_pe     = (const float*)d_in[4];
    const float* b_pe     = (const float*)d_in[5];
    const float* W_ch     = (const float*)d_in[6];
    const float* b_ch     = (const float*)d_in[7];
    const float* W_node   = (const float*)d_in[8];
    const float* b_node   = (const float*)d_in[9];
    const float* W_edge   = (const float*)d_in[10];
    const float* b_edge   = (const float*)d_in[11];
    const float* g_nodes  = (const float*)d_in[12];
    const float* bn_nodes = (const float*)d_in[13];
    const float* g_edges  = (const float*)d_in[14];
    const float* bn_edges = (const float*)d_in[15];

    float* out  = (float*)d_out;
    float* outV = out;
    float* outE = out + (size_t)NODES*128;
    float* outI = out + (size_t)NODES*128 + (size_t)NEDGE*128;

    k_prepA<<<32, 256>>>(X);
    k_prepB<<<45, 256>>>(W_pe, b_pe, W_ch, b_ch, W_edge);
    k_topk <<<NODES, 256>>>(resid, chain, b_edge, g_edges, bn_edges, outE, outI);
    k_node <<<NODES/8, 256>>>(W_node, b_node, g_nodes, bn_nodes, outV);
}